// round 8
// baseline (speedup 1.0000x reference)
#include <cuda_runtime.h>
#include <cuda_fp16.h>
#include <cstdint>

#define NN 100000
#define NE 1600000
#define NB_SCAN ((NN + 1023) / 1024)

// Static scratch (no allocations allowed)
__device__ __half g_fH[(size_t)NN * 128];  // projected features (fp16 gather payload)
__device__ float  g_fB[(size_t)NN * 128];  // inter-layer node features (fp32)
__device__ float  g_el[NN * 4];
__device__ float  g_er[NN * 4];
__device__ int    g_deg[NN];
__device__ int    g_off[NN + 1];
__device__ int    g_esrc[NE];
__device__ int    g_bsum[NB_SCAN];
__device__ int    g_boff[NB_SCAN];

// ---------------------------------------------------------------------------
// packed f32x2 helpers
__device__ __forceinline__ uint64_t dup_f32(float a) {
    uint64_t r;
    asm("mov.b64 %0, {%1, %1};" : "=l"(r) : "f"(a));
    return r;
}
__device__ __forceinline__ void fma2(uint64_t& c, uint64_t a, uint64_t b) {
    asm("fma.rn.f32x2 %0, %1, %2, %0;" : "+l"(c) : "l"(a), "l"(b));
}
__device__ __forceinline__ float2 unpk(uint64_t v) {
    float2 r;
    asm("mov.b64 {%0, %1}, %2;" : "=f"(r.x), "=f"(r.y) : "l"(v));
    return r;
}

// ===========================================================================
// CSR build: histogram -> scan -> scatter
// ===========================================================================
__global__ void hist_kernel(const int* __restrict__ dst, int* __restrict__ deg, int E) {
    int i = blockIdx.x * blockDim.x + threadIdx.x;
    if (i < E) atomicAdd(&deg[dst[i]], 1);
}

__global__ void bsum_kernel(const int* __restrict__ deg, int* __restrict__ bsum, int n) {
    __shared__ int sm[256];
    int base = blockIdx.x * 1024;
    int t = threadIdx.x;
    int s = 0;
    for (int j = 0; j < 4; j++) {
        int idx = base + t + j * 256;
        if (idx < n) s += deg[idx];
    }
    sm[t] = s;
    __syncthreads();
    for (int d = 128; d > 0; d >>= 1) {
        if (t < d) sm[t] += sm[t + d];
        __syncthreads();
    }
    if (t == 0) bsum[blockIdx.x] = sm[0];
}

__global__ void bscan_kernel(const int* __restrict__ bsum, int* __restrict__ boff,
                             int* __restrict__ off, int nb, int n) {
    __shared__ int sm[128];
    int t = threadIdx.x;
    sm[t] = (t < nb) ? bsum[t] : 0;
    __syncthreads();
    for (int d = 1; d < 128; d <<= 1) {
        int x = (t >= d) ? sm[t - d] : 0;
        __syncthreads();
        sm[t] += x;
        __syncthreads();
    }
    if (t < nb) boff[t] = (t > 0) ? sm[t - 1] : 0;
    if (t == 127) off[n] = sm[127];
}

__global__ void scan_chunk_kernel(const int* __restrict__ deg, const int* __restrict__ boff,
                                  int* __restrict__ off, int n) {
    __shared__ int sm[256];
    int base = blockIdx.x * 1024;
    int t = threadIdx.x;
    int v[4];
    int s = 0;
    for (int j = 0; j < 4; j++) {
        int idx = base + t * 4 + j;
        v[j] = (idx < n) ? deg[idx] : 0;
        s += v[j];
    }
    sm[t] = s;
    __syncthreads();
    for (int d = 1; d < 256; d <<= 1) {
        int x = (t >= d) ? sm[t - d] : 0;
        __syncthreads();
        sm[t] += x;
        __syncthreads();
    }
    int run = ((t > 0) ? sm[t - 1] : 0) + boff[blockIdx.x];
    for (int j = 0; j < 4; j++) {
        int idx = base + t * 4 + j;
        if (idx < n) off[idx] = run;
        run += v[j];
    }
}

__global__ void scatter_kernel(const int* __restrict__ src, const int* __restrict__ dst,
                               const int* __restrict__ off, int* __restrict__ cursor,
                               int* __restrict__ esrc, int E) {
    int i = blockIdx.x * blockDim.x + threadIdx.x;
    if (i >= E) return;
    int dn = dst[i];
    int pos = off[dn] + atomicAdd(&cursor[dn], 1);
    esrc[pos] = src[i];
}

// ===========================================================================
// Fused GEMM + attention scores: F(half) = X @ W; el/er from fp32 result.
// ===========================================================================
template <int COLS, int H>
__global__ void gemm_attn_kernel(const float* __restrict__ X, const float* __restrict__ W,
                                 const float* __restrict__ al, const float* __restrict__ ar,
                                 __half* __restrict__ F, float* __restrict__ el,
                                 float* __restrict__ er, int nrows) {
    constexpr int K    = 128;
    constexpr int BR   = 64;
    constexpr int XPAD = BR + 4;
    extern __shared__ float sm[];
    float* Xs = sm;                  // [K][XPAD], transposed
    float* Ws = sm + K * XPAD;       // [K][COLS]

    const int tid  = threadIdx.x;
    const int nth  = blockDim.x;
    const int row0 = blockIdx.x * BR;

    for (int i = tid; i < K * COLS / 4; i += nth)
        ((float4*)Ws)[i] = ((const float4*)W)[i];

    for (int i = tid; i < BR * (K / 4); i += nth) {
        int r  = i / (K / 4);
        int k4 = i % (K / 4);
        int row = row0 + r;
        float4 v = make_float4(0.f, 0.f, 0.f, 0.f);
        if (row < nrows) v = ((const float4*)(X + (size_t)row * K))[k4];
        Xs[(k4 * 4 + 0) * XPAD + r] = v.x;
        Xs[(k4 * 4 + 1) * XPAD + r] = v.y;
        Xs[(k4 * 4 + 2) * XPAD + r] = v.z;
        Xs[(k4 * 4 + 3) * XPAD + r] = v.w;
    }
    __syncthreads();

    const int rc = tid % 16;
    const int cc = tid / 16;

    uint64_t acc2[4][4] = {};

#pragma unroll 4
    for (int k = 0; k < K; k++) {
        float4 a4 = *(const float4*)&Xs[k * XPAD + rc * 4];
        const ulonglong2* bp = (const ulonglong2*)&Ws[k * COLS + cc * 8];
        ulonglong2 b01 = bp[0];
        ulonglong2 b23 = bp[1];
        uint64_t a0 = dup_f32(a4.x), a1 = dup_f32(a4.y);
        uint64_t a2 = dup_f32(a4.z), a3 = dup_f32(a4.w);
        fma2(acc2[0][0], a0, b01.x); fma2(acc2[0][1], a0, b01.y);
        fma2(acc2[0][2], a0, b23.x); fma2(acc2[0][3], a0, b23.y);
        fma2(acc2[1][0], a1, b01.x); fma2(acc2[1][1], a1, b01.y);
        fma2(acc2[1][2], a1, b23.x); fma2(acc2[1][3], a1, b23.y);
        fma2(acc2[2][0], a2, b01.x); fma2(acc2[2][1], a2, b01.y);
        fma2(acc2[2][2], a2, b23.x); fma2(acc2[2][3], a2, b23.y);
        fma2(acc2[3][0], a3, b01.x); fma2(acc2[3][1], a3, b01.y);
        fma2(acc2[3][2], a3, b23.x); fma2(acc2[3][3], a3, b23.y);
    }

    float al8[8], ar8[8];
#pragma unroll
    for (int j = 0; j < 8; j++) {
        al8[j] = __ldg(al + cc * 8 + j);
        ar8[j] = __ldg(ar + cc * 8 + j);
    }

    float slp[4], srp[4];
#pragma unroll
    for (int i = 0; i < 4; i++) {
        float o[8];
#pragma unroll
        for (int j2 = 0; j2 < 4; j2++) {
            float2 p = unpk(acc2[i][j2]);
            o[2 * j2] = p.x; o[2 * j2 + 1] = p.y;
        }
        int row = row0 + rc * 4 + i;
        if (row < nrows) {
            __half2 h0 = __floats2half2_rn(o[0], o[1]);
            __half2 h1 = __floats2half2_rn(o[2], o[3]);
            __half2 h2 = __floats2half2_rn(o[4], o[5]);
            __half2 h3 = __floats2half2_rn(o[6], o[7]);
            uint4 u;
            u.x = *(uint32_t*)&h0; u.y = *(uint32_t*)&h1;
            u.z = *(uint32_t*)&h2; u.w = *(uint32_t*)&h3;
            *(uint4*)(F + (size_t)row * COLS + cc * 8) = u;
        }
        float sl = 0.f, sr = 0.f;
#pragma unroll
        for (int j = 0; j < 8; j++) { sl = fmaf(o[j], al8[j], sl); sr = fmaf(o[j], ar8[j], sr); }
        slp[i] = sl; srp[i] = sr;
    }

    __syncthreads();
    float* red = sm;            // [BR][H][2]
    for (int i = tid; i < BR * H * 2; i += nth) red[i] = 0.f;
    __syncthreads();
    int h = (H == 1) ? 0 : (cc * 8) / 32;
#pragma unroll
    for (int i = 0; i < 4; i++) {
        int r = rc * 4 + i;
        atomicAdd(&red[(r * H + h) * 2 + 0], slp[i]);
        atomicAdd(&red[(r * H + h) * 2 + 1], srp[i]);
    }
    __syncthreads();
    for (int i = tid; i < BR * H; i += nth) {
        int r = i / H, hh = i % H;
        int row = row0 + r;
        if (row < nrows) {
            el[row * H + hh] = red[i * 2 + 0];
            er[row * H + hh] = red[i * 2 + 1];
        }
    }
}

// ===========================================================================
// CSR edge aggregation + fused normalize/bias/ELU. One warp per dst node.
// Explicit 4-wide software pipeline: broadcast 4 src indices, issue all 8
// loads (4x el + 4x payload) before consuming -> MLP~8 per warp.
// Tail edges use a safe replicated address with w forced to 0.
// (segment-max shift dropped: alpha = w/s invariant; scores O(1))
// ===========================================================================
template <int H, bool ELU>
__global__ void edge_csr_kernel(const __half* __restrict__ F, const float* __restrict__ el,
                                const float* __restrict__ er, const int* __restrict__ off,
                                const int* __restrict__ esrc, const float* __restrict__ b,
                                float* __restrict__ out, int n) {
    constexpr int HD = H * 32;
    int warp = (blockIdx.x * blockDim.x + threadIdx.x) >> 5;
    int lane = threadIdx.x & 31;
    if (warp >= n) return;
    const int node = warp;

    float erh;
    if (H == 4) {
        float4 e4 = *(const float4*)(er + node * 4);
        erh = lane < 8 ? e4.x : lane < 16 ? e4.y : lane < 24 ? e4.z : e4.w;
    } else {
        erh = __ldg(er + node);
    }

    const int start = off[node], end = off[node + 1];
    float acc0 = 0.f, acc1 = 0.f, acc2 = 0.f, acc3 = 0.f, s = 0.f;

    for (int base = start; base < end; base += 32) {
        int cnt = min(32, end - base);
        int sidx = (base + lane < end) ? __ldg(esrc + base + lane) : 0;

        for (int j = 0; j < cnt; j += 4) {
            // broadcast 4 indices (invalid -> replicate edge j, weight 0)
            int sn0 = __shfl_sync(0xffffffffu, sidx, j);
            int sn1 = __shfl_sync(0xffffffffu, sidx, min(j + 1, cnt - 1));
            int sn2 = __shfl_sync(0xffffffffu, sidx, min(j + 2, cnt - 1));
            int sn3 = __shfl_sync(0xffffffffu, sidx, min(j + 3, cnt - 1));
            bool v1 = (j + 1 < cnt), v2 = (j + 2 < cnt), v3 = (j + 3 < cnt);

            float el0, el1, el2, el3;
            if (H == 4) {
                float4 a = *(const float4*)(el + sn0 * 4);
                float4 b4 = *(const float4*)(el + sn1 * 4);
                float4 c = *(const float4*)(el + sn2 * 4);
                float4 d = *(const float4*)(el + sn3 * 4);
                el0 = lane < 8 ? a.x : lane < 16 ? a.y : lane < 24 ? a.z : a.w;
                el1 = lane < 8 ? b4.x : lane < 16 ? b4.y : lane < 24 ? b4.z : b4.w;
                el2 = lane < 8 ? c.x : lane < 16 ? c.y : lane < 24 ? c.z : c.w;
                el3 = lane < 8 ? d.x : lane < 16 ? d.y : lane < 24 ? d.z : d.w;
            } else {
                el0 = __ldg(el + sn0); el1 = __ldg(el + sn1);
                el2 = __ldg(el + sn2); el3 = __ldg(el + sn3);
            }

            uint2 p0, p1, p2, p3;
            uint32_t q0, q1, q2, q3;
            if (H == 4) {
                p0 = *(const uint2*)(F + (size_t)sn0 * 128 + lane * 4);
                p1 = *(const uint2*)(F + (size_t)sn1 * 128 + lane * 4);
                p2 = *(const uint2*)(F + (size_t)sn2 * 128 + lane * 4);
                p3 = *(const uint2*)(F + (size_t)sn3 * 128 + lane * 4);
            } else {
                q0 = *(const uint32_t*)(F + (size_t)sn0 * 32 + lane * 0) ;
                // H==1: lane loads a single half; use half-width loads
                q0 = (uint32_t)*(const uint16_t*)(F + (size_t)sn0 * 32 + lane);
                q1 = (uint32_t)*(const uint16_t*)(F + (size_t)sn1 * 32 + lane);
                q2 = (uint32_t)*(const uint16_t*)(F + (size_t)sn2 * 32 + lane);
                q3 = (uint32_t)*(const uint16_t*)(F + (size_t)sn3 * 32 + lane);
            }

            float w0, w1, w2, w3;
            {
                float v = el0 + erh; v = v > 0.f ? v : 0.2f * v; w0 = __expf(v);
            }
            { float v = el1 + erh; v = v > 0.f ? v : 0.2f * v; w1 = v1 ? __expf(v) : 0.f; }
            { float v = el2 + erh; v = v > 0.f ? v : 0.2f * v; w2 = v2 ? __expf(v) : 0.f; }
            { float v = el3 + erh; v = v > 0.f ? v : 0.2f * v; w3 = v3 ? __expf(v) : 0.f; }
            s += (w0 + w1) + (w2 + w3);

            if (H == 4) {
                float2 f0a = __half22float2(*(__half2*)&p0.x);
                float2 f0b = __half22float2(*(__half2*)&p0.y);
                acc0 = fmaf(w0, f0a.x, acc0); acc1 = fmaf(w0, f0a.y, acc1);
                acc2 = fmaf(w0, f0b.x, acc2); acc3 = fmaf(w0, f0b.y, acc3);
                float2 f1a = __half22float2(*(__half2*)&p1.x);
                float2 f1b = __half22float2(*(__half2*)&p1.y);
                acc0 = fmaf(w1, f1a.x, acc0); acc1 = fmaf(w1, f1a.y, acc1);
                acc2 = fmaf(w1, f1b.x, acc2); acc3 = fmaf(w1, f1b.y, acc3);
                float2 f2a = __half22float2(*(__half2*)&p2.x);
                float2 f2b = __half22float2(*(__half2*)&p2.y);
                acc0 = fmaf(w2, f2a.x, acc0); acc1 = fmaf(w2, f2a.y, acc1);
                acc2 = fmaf(w2, f2b.x, acc2); acc3 = fmaf(w2, f2b.y, acc3);
                float2 f3a = __half22float2(*(__half2*)&p3.x);
                float2 f3b = __half22float2(*(__half2*)&p3.y);
                acc0 = fmaf(w3, f3a.x, acc0); acc1 = fmaf(w3, f3a.y, acc1);
                acc2 = fmaf(w3, f3b.x, acc2); acc3 = fmaf(w3, f3b.y, acc3);
            } else {
                uint16_t u0 = (uint16_t)q0, u1 = (uint16_t)q1;
                uint16_t u2 = (uint16_t)q2, u3 = (uint16_t)q3;
                acc0 = fmaf(w0, __half2float(*(__half*)&u0), acc0);
                acc0 = fmaf(w1, __half2float(*(__half*)&u1), acc0);
                acc0 = fmaf(w2, __half2float(*(__half*)&u2), acc0);
                acc0 = fmaf(w3, __half2float(*(__half*)&u3), acc0);
            }
        }
    }

    float inv = 1.f / fmaxf(s, 1e-9f);
    if (H == 4) {
        int c = lane * 4;
        float4 o;
        o.x = acc0 * inv + b[c + 0];
        o.y = acc1 * inv + b[c + 1];
        o.z = acc2 * inv + b[c + 2];
        o.w = acc3 * inv + b[c + 3];
        if (ELU) {
            o.x = o.x > 0.f ? o.x : expm1f(o.x);
            o.y = o.y > 0.f ? o.y : expm1f(o.y);
            o.z = o.z > 0.f ? o.z : expm1f(o.z);
            o.w = o.w > 0.f ? o.w : expm1f(o.w);
        }
        *(float4*)(out + (size_t)node * HD + c) = o;
    } else {
        float o = acc0 * inv + b[lane];
        if (ELU) o = o > 0.f ? o : expm1f(o);
        out[(size_t)node * HD + lane] = o;
    }
}

// ===========================================================================
extern "C" void kernel_launch(void* const* d_in, const int* in_sizes, int n_in,
                              void* d_out, int out_size) {
    const float* x   = (const float*)d_in[0];
    const int*   src = (const int*)d_in[1];
    const int*   dst = (const int*)d_in[2];
    const float* W1  = (const float*)d_in[3];
    const float* al1 = (const float*)d_in[4];
    const float* ar1 = (const float*)d_in[5];
    const float* b1  = (const float*)d_in[6];
    const float* W2  = (const float*)d_in[7];
    const float* al2 = (const float*)d_in[8];
    const float* ar2 = (const float*)d_in[9];
    const float* b2  = (const float*)d_in[10];
    const float* W3  = (const float*)d_in[11];
    const float* al3 = (const float*)d_in[12];
    const float* ar3 = (const float*)d_in[13];
    const float* b3  = (const float*)d_in[14];
    float* out = (float*)d_out;

    const int N = in_sizes[0] / 128;
    const int E = in_sizes[1];

    __half* fH;
    float *fB, *el, *er;
    int *deg, *off, *esrc, *bsum, *boff;
    cudaGetSymbolAddress((void**)&fH, g_fH);
    cudaGetSymbolAddress((void**)&fB, g_fB);
    cudaGetSymbolAddress((void**)&el, g_el);
    cudaGetSymbolAddress((void**)&er, g_er);
    cudaGetSymbolAddress((void**)&deg, g_deg);
    cudaGetSymbolAddress((void**)&off, g_off);
    cudaGetSymbolAddress((void**)&esrc, g_esrc);
    cudaGetSymbolAddress((void**)&bsum, g_bsum);
    cudaGetSymbolAddress((void**)&boff, g_boff);

    const int SMEM128 = (128 * 68 + 128 * 128) * (int)sizeof(float);
    const int SMEM32  = (128 * 68 + 128 * 32)  * (int)sizeof(float);
    cudaFuncSetAttribute((const void*)gemm_attn_kernel<128, 4>,
                         cudaFuncAttributeMaxDynamicSharedMemorySize, SMEM128);
    cudaFuncSetAttribute((const void*)gemm_attn_kernel<32, 1>,
                         cudaFuncAttributeMaxDynamicSharedMemorySize, SMEM32);

    const int gemm_blocks = (N + 63) / 64;
    const int eblk = (E + 255) / 256;
    const int nb   = (N + 1023) / 1024;
    const int edge_blocks = (N * 32 + 255) / 256;

    // ---------------- CSR build (reused by all 3 layers) ----------------
    cudaMemsetAsync(deg, 0, (size_t)N * sizeof(int));
    hist_kernel<<<eblk, 256>>>(dst, deg, E);
    bsum_kernel<<<nb, 256>>>(deg, bsum, N);
    bscan_kernel<<<1, 128>>>(bsum, boff, off, nb, N);
    scan_chunk_kernel<<<nb, 256>>>(deg, boff, off, N);
    cudaMemsetAsync(deg, 0, (size_t)N * sizeof(int));
    scatter_kernel<<<eblk, 256>>>(src, dst, off, deg, esrc, E);

    // ---------------- Layer 1 ----------------
    gemm_attn_kernel<128, 4><<<gemm_blocks, 256, SMEM128>>>(
        x, W1, al1, ar1, fH, el, er, N);
    edge_csr_kernel<4, true><<<edge_blocks, 256>>>(fH, el, er, off, esrc, b1, fB, N);

    // ---------------- Layer 2 ----------------
    gemm_attn_kernel<128, 4><<<gemm_blocks, 256, SMEM128>>>(
        fB, W2, al2, ar2, fH, el, er, N);
    edge_csr_kernel<4, true><<<edge_blocks, 256>>>(fH, el, er, off, esrc, b2, fB, N);

    // ---------------- Layer 3 ----------------
    gemm_attn_kernel<32, 1><<<gemm_blocks, 64, SMEM32>>>(
        fB, W3, al3, ar3, fH, el, er, N);
    edge_csr_kernel<1, false><<<edge_blocks, 256>>>(fH, el, er, off, esrc, b3, out, N);
}

// round 9
// speedup vs baseline: 1.5680x; 1.5680x over previous
#include <cuda_runtime.h>
#include <cuda_fp16.h>
#include <cstdint>

#define NN 100000
#define NE 1600000
#define NB_SCAN ((NN + 1023) / 1024)

// Static scratch (no allocations allowed)
__device__ __half g_xH[(size_t)NN * 128];   // fp16 layer-1 input
__device__ __half g_fH[(size_t)NN * 128];   // GEMM output (edge gather payload)
__device__ __half g_hH[(size_t)NN * 128];   // edge output (next-layer GEMM input)
__device__ float  g_el[NN * 4];
__device__ float  g_er[NN * 4];
__device__ __half g_wth[16384 * 2 + 4096];  // W hi, transposed [n][k], 3 layers
__device__ __half g_wtl[16384 * 2 + 4096];  // W lo
__device__ int    g_deg[NN];
__device__ int    g_off[NN + 1];
__device__ int    g_esrc[NE];
__device__ int    g_bsum[NB_SCAN];
__device__ int    g_boff[NB_SCAN];

// ===========================================================================
// CSR build: histogram -> scan -> scatter
// ===========================================================================
__global__ void hist_kernel(const int* __restrict__ dst, int* __restrict__ deg, int E) {
    int i = blockIdx.x * blockDim.x + threadIdx.x;
    if (i < E) atomicAdd(&deg[dst[i]], 1);
}

__global__ void bsum_kernel(const int* __restrict__ deg, int* __restrict__ bsum, int n) {
    __shared__ int sm[256];
    int base = blockIdx.x * 1024;
    int t = threadIdx.x;
    int s = 0;
    for (int j = 0; j < 4; j++) {
        int idx = base + t + j * 256;
        if (idx < n) s += deg[idx];
    }
    sm[t] = s;
    __syncthreads();
    for (int d = 128; d > 0; d >>= 1) {
        if (t < d) sm[t] += sm[t + d];
        __syncthreads();
    }
    if (t == 0) bsum[blockIdx.x] = sm[0];
}

__global__ void bscan_kernel(const int* __restrict__ bsum, int* __restrict__ boff,
                             int* __restrict__ off, int nb, int n) {
    __shared__ int sm[128];
    int t = threadIdx.x;
    sm[t] = (t < nb) ? bsum[t] : 0;
    __syncthreads();
    for (int d = 1; d < 128; d <<= 1) {
        int x = (t >= d) ? sm[t - d] : 0;
        __syncthreads();
        sm[t] += x;
        __syncthreads();
    }
    if (t < nb) boff[t] = (t > 0) ? sm[t - 1] : 0;
    if (t == 127) off[n] = sm[127];
}

__global__ void scan_chunk_kernel(const int* __restrict__ deg, const int* __restrict__ boff,
                                  int* __restrict__ off, int n) {
    __shared__ int sm[256];
    int base = blockIdx.x * 1024;
    int t = threadIdx.x;
    int v[4];
    int s = 0;
    for (int j = 0; j < 4; j++) {
        int idx = base + t * 4 + j;
        v[j] = (idx < n) ? deg[idx] : 0;
        s += v[j];
    }
    sm[t] = s;
    __syncthreads();
    for (int d = 1; d < 256; d <<= 1) {
        int x = (t >= d) ? sm[t - d] : 0;
        __syncthreads();
        sm[t] += x;
        __syncthreads();
    }
    int run = ((t > 0) ? sm[t - 1] : 0) + boff[blockIdx.x];
    for (int j = 0; j < 4; j++) {
        int idx = base + t * 4 + j;
        if (idx < n) off[idx] = run;
        run += v[j];
    }
}

__global__ void scatter_kernel(const int* __restrict__ src, const int* __restrict__ dst,
                               const int* __restrict__ off, int* __restrict__ cursor,
                               int* __restrict__ esrc, int E) {
    int i = blockIdx.x * blockDim.x + threadIdx.x;
    if (i >= E) return;
    int dn = dst[i];
    int pos = off[dn] + atomicAdd(&cursor[dn], 1);
    esrc[pos] = src[i];
}

// ===========================================================================
// Precision prep: x -> fp16; W (fp32 [k][n]) -> hi/lo fp16 transposed [n][128]
// ===========================================================================
__global__ void conv_x_kernel(const float* __restrict__ x, __half* __restrict__ xh, int n4) {
    int i = blockIdx.x * blockDim.x + threadIdx.x;
    if (i >= n4) return;
    float4 v = ((const float4*)x)[i];
    __half2 h0 = __floats2half2_rn(v.x, v.y);
    __half2 h1 = __floats2half2_rn(v.z, v.w);
    uint2 u;
    u.x = *(uint32_t*)&h0; u.y = *(uint32_t*)&h1;
    ((uint2*)xh)[i] = u;
}

__global__ void conv_w_kernel(const float* __restrict__ W, __half* __restrict__ hi,
                              __half* __restrict__ lo, int cols) {
    int i = blockIdx.x * blockDim.x + threadIdx.x;
    if (i >= 128 * cols) return;
    int k = i / cols, n = i % cols;
    float w = W[i];
    __half h = __float2half_rn(w);
    float r = w - __half2float(h);
    hi[n * 128 + k] = h;
    lo[n * 128 + k] = __float2half_rn(r);
}

// ===========================================================================
// Tensor-core GEMM (mma.sync m16n8k16, fp16 in / fp32 acc) + attn epilogue.
// F[N,COLS] = A[N,128] @ (Whi+Wlo); el/er = row-dot(F, al/ar) per head.
// Block: 128 rows x COLS, 256 threads (8 warps).
// ===========================================================================
__device__ __forceinline__ void mma16816(float* c, const uint32_t* a, uint32_t b0, uint32_t b1) {
    asm volatile(
        "mma.sync.aligned.m16n8k16.row.col.f32.f16.f16.f32 "
        "{%0,%1,%2,%3}, {%4,%5,%6,%7}, {%8,%9}, {%0,%1,%2,%3};"
        : "+f"(c[0]), "+f"(c[1]), "+f"(c[2]), "+f"(c[3])
        : "r"(a[0]), "r"(a[1]), "r"(a[2]), "r"(a[3]), "r"(b0), "r"(b1));
}

template <int COLS>
__global__ __launch_bounds__(256) void gemm_mma_kernel(
    const __half* __restrict__ A, const __half* __restrict__ Wth,
    const __half* __restrict__ Wtl, const float* __restrict__ al,
    const float* __restrict__ ar, __half* __restrict__ F,
    float* __restrict__ el, float* __restrict__ er, int nrows) {
    constexpr int MW  = (COLS == 128) ? 4 : 8;   // warps in M
    constexpr int NW  = (COLS == 128) ? 2 : 1;   // warps in N
    constexpr int WM  = (COLS == 128) ? 2 : 1;   // m16 frags per warp
    constexpr int WN  = (COLS == 128) ? 8 : 4;   // n8 frags per warp
    constexpr int NHL = (COLS == 128) ? 2 : 1;   // heads per warp
    constexpr int HT  = COLS / 32;               // total heads
    constexpr int ST  = 136;                     // smem stride (halves), 17 uint4

    extern __shared__ __half smh[];
    __half* As = smh;                 // [128][ST]
    __half* Wh = smh + 128 * ST;      // [COLS][ST]
    __half* Wl = Wh + COLS * ST;      // [COLS][ST]

    const int tid  = threadIdx.x;
    const int wid  = tid >> 5;
    const int lane = tid & 31;
    const int row0 = blockIdx.x * 128;

    for (int i = tid; i < 128 * 16; i += 256) {
        int r = i >> 4, q = i & 15;
        uint4 v = make_uint4(0, 0, 0, 0);
        if (row0 + r < nrows) v = ((const uint4*)(A + (size_t)(row0 + r) * 128))[q];
        ((uint4*)(As + r * ST))[q] = v;
    }
    for (int i = tid; i < COLS * 16; i += 256) {
        int r = i >> 4, q = i & 15;
        ((uint4*)(Wh + r * ST))[q] = ((const uint4*)(Wth + r * 128))[q];
        ((uint4*)(Wl + r * ST))[q] = ((const uint4*)(Wtl + r * 128))[q];
    }
    __syncthreads();

    const int m_warp = wid % MW, n_warp = wid / MW;
    const int wm = m_warp * WM * 16, wn = n_warp * WN * 8;
    const int qr = lane >> 2, qc = (lane & 3) * 2;

    float acc[WM][WN][4] = {};

#pragma unroll
    for (int kk = 0; kk < 8; kk++) {
        const int k0 = kk * 16 + qc;
        uint32_t a[WM][4];
#pragma unroll
        for (int im = 0; im < WM; im++) {
            const __half* p = As + (wm + im * 16 + qr) * ST;
            a[im][0] = *(const uint32_t*)(p + k0);
            a[im][1] = *(const uint32_t*)(p + 8 * ST + k0);
            a[im][2] = *(const uint32_t*)(p + k0 + 8);
            a[im][3] = *(const uint32_t*)(p + 8 * ST + k0 + 8);
        }
#pragma unroll
        for (int jn = 0; jn < WN; jn++) {
            const __half* ph = Wh + (wn + jn * 8 + qr) * ST;
            const __half* pl = Wl + (wn + jn * 8 + qr) * ST;
            uint32_t bh0 = *(const uint32_t*)(ph + k0);
            uint32_t bh1 = *(const uint32_t*)(ph + k0 + 8);
            uint32_t bl0 = *(const uint32_t*)(pl + k0);
            uint32_t bl1 = *(const uint32_t*)(pl + k0 + 8);
#pragma unroll
            for (int im = 0; im < WM; im++) {
                mma16816(acc[im][jn], a[im], bh0, bh1);
                mma16816(acc[im][jn], a[im], bl0, bl1);
            }
        }
    }

    // epilogue: F store (fp16) + per-row el/er partials
    float elp[WM][2][NHL] = {};
    float erp[WM][2][NHL] = {};
#pragma unroll
    for (int jn = 0; jn < WN; jn++) {
        int c = wn + jn * 8 + qc;
        float2 alv = *(const float2*)(al + c);
        float2 arv = *(const float2*)(ar + c);
        int hl = jn >> 2;   // 4 n-frags = 32 cols = 1 head
#pragma unroll
        for (int im = 0; im < WM; im++) {
            float* a4 = acc[im][jn];
            elp[im][0][hl] += a4[0] * alv.x + a4[1] * alv.y;
            erp[im][0][hl] += a4[0] * arv.x + a4[1] * arv.y;
            elp[im][1][hl] += a4[2] * alv.x + a4[3] * alv.y;
            erp[im][1][hl] += a4[2] * arv.x + a4[3] * arv.y;
            int r = row0 + wm + im * 16 + qr;
            if (r < nrows) {
                __half2 h = __floats2half2_rn(a4[0], a4[1]);
                *(__half2*)(F + (size_t)r * COLS + c) = h;
            }
            if (r + 8 < nrows) {
                __half2 h = __floats2half2_rn(a4[2], a4[3]);
                *(__half2*)(F + (size_t)(r + 8) * COLS + c) = h;
            }
        }
    }

    // quad reduction (lanes sharing a row differ only in lane&3)
#pragma unroll
    for (int im = 0; im < WM; im++)
#pragma unroll
        for (int rr = 0; rr < 2; rr++)
#pragma unroll
            for (int hl = 0; hl < NHL; hl++) {
                float v = elp[im][rr][hl];
                v += __shfl_xor_sync(0xffffffffu, v, 1);
                v += __shfl_xor_sync(0xffffffffu, v, 2);
                elp[im][rr][hl] = v;
                float u = erp[im][rr][hl];
                u += __shfl_xor_sync(0xffffffffu, u, 1);
                u += __shfl_xor_sync(0xffffffffu, u, 2);
                erp[im][rr][hl] = u;
            }
    if ((lane & 3) == 0) {
#pragma unroll
        for (int im = 0; im < WM; im++)
#pragma unroll
            for (int rr = 0; rr < 2; rr++) {
                int r = row0 + wm + im * 16 + qr + rr * 8;
                if (r < nrows) {
#pragma unroll
                    for (int hl = 0; hl < NHL; hl++) {
                        int hg = n_warp * NHL + hl;
                        el[r * HT + hg] = elp[im][rr][hl];
                        er[r * HT + hg] = erp[im][rr][hl];
                    }
                }
            }
    }
}

// ===========================================================================
// CSR edge aggregation + fused normalize/bias/ELU. One warp per dst node.
// (segment-max shift dropped: alpha = w/s invariant; scores O(1))
// ===========================================================================
template <int H, bool ELU, bool HALF_OUT>
__global__ void edge_csr_kernel(const __half* __restrict__ F, const float* __restrict__ el,
                                const float* __restrict__ er, const int* __restrict__ off,
                                const int* __restrict__ esrc, const float* __restrict__ b,
                                void* __restrict__ outv, int n) {
    constexpr int HD = H * 32;
    int warp = (blockIdx.x * blockDim.x + threadIdx.x) >> 5;
    int lane = threadIdx.x & 31;
    if (warp >= n) return;
    const int node = warp;

    float erh;
    if (H == 4) {
        float4 e4 = *(const float4*)(er + node * 4);
        erh = lane < 8 ? e4.x : lane < 16 ? e4.y : lane < 24 ? e4.z : e4.w;
    } else {
        erh = __ldg(er + node);
    }

    const int start = off[node], end = off[node + 1];
    float acc0 = 0.f, acc1 = 0.f, acc2 = 0.f, acc3 = 0.f, s = 0.f;

    for (int base = start; base < end; base += 32) {
        int cnt = min(32, end - base);
        int sidx = (base + lane < end) ? __ldg(esrc + base + lane) : 0;
#pragma unroll 4
        for (int j = 0; j < cnt; j++) {
            int sn = __shfl_sync(0xffffffffu, sidx, j);
            float elh;
            if (H == 4) {
                float4 e4 = *(const float4*)(el + sn * 4);
                elh = lane < 8 ? e4.x : lane < 16 ? e4.y : lane < 24 ? e4.z : e4.w;
            } else {
                elh = __ldg(el + sn);
            }
            float v = elh + erh;
            v = v > 0.f ? v : 0.2f * v;
            float w = __expf(v);
            s += w;
            if (H == 4) {
                uint2 p = *(const uint2*)(F + (size_t)sn * 128 + lane * 4);
                float2 f0 = __half22float2(*(__half2*)&p.x);
                float2 f1 = __half22float2(*(__half2*)&p.y);
                acc0 = fmaf(w, f0.x, acc0);
                acc1 = fmaf(w, f0.y, acc1);
                acc2 = fmaf(w, f1.x, acc2);
                acc3 = fmaf(w, f1.y, acc3);
            } else {
                float f = __half2float(__ldg(F + (size_t)sn * 32 + lane));
                acc0 = fmaf(w, f, acc0);
            }
        }
    }

    float inv = 1.f / fmaxf(s, 1e-9f);
    if (H == 4) {
        int c = lane * 4;
        float4 o;
        o.x = acc0 * inv + b[c + 0];
        o.y = acc1 * inv + b[c + 1];
        o.z = acc2 * inv + b[c + 2];
        o.w = acc3 * inv + b[c + 3];
        if (ELU) {
            o.x = o.x > 0.f ? o.x : expm1f(o.x);
            o.y = o.y > 0.f ? o.y : expm1f(o.y);
            o.z = o.z > 0.f ? o.z : expm1f(o.z);
            o.w = o.w > 0.f ? o.w : expm1f(o.w);
        }
        if (HALF_OUT) {
            __half2 h0 = __floats2half2_rn(o.x, o.y);
            __half2 h1 = __floats2half2_rn(o.z, o.w);
            uint2 u;
            u.x = *(uint32_t*)&h0; u.y = *(uint32_t*)&h1;
            ((uint2*)((__half*)outv + (size_t)node * HD))[lane] = u;
        } else {
            *(float4*)((float*)outv + (size_t)node * HD + c) = o;
        }
    } else {
        float o = acc0 * inv + b[lane];
        if (ELU) o = o > 0.f ? o : expm1f(o);
        ((float*)outv)[(size_t)node * HD + lane] = o;
    }
}

// ===========================================================================
extern "C" void kernel_launch(void* const* d_in, const int* in_sizes, int n_in,
                              void* d_out, int out_size) {
    const float* x   = (const float*)d_in[0];
    const int*   src = (const int*)d_in[1];
    const int*   dst = (const int*)d_in[2];
    const float* W1  = (const float*)d_in[3];
    const float* al1 = (const float*)d_in[4];
    const float* ar1 = (const float*)d_in[5];
    const float* b1  = (const float*)d_in[6];
    const float* W2  = (const float*)d_in[7];
    const float* al2 = (const float*)d_in[8];
    const float* ar2 = (const float*)d_in[9];
    const float* b2  = (const float*)d_in[10];
    const float* W3  = (const float*)d_in[11];
    const float* al3 = (const float*)d_in[12];
    const float* ar3 = (const float*)d_in[13];
    const float* b3  = (const float*)d_in[14];
    float* out = (float*)d_out;

    const int N = in_sizes[0] / 128;
    const int E = in_sizes[1];

    __half *xH, *fH, *hH, *wth, *wtl;
    float *el, *er;
    int *deg, *off, *esrc, *bsum, *boff;
    cudaGetSymbolAddress((void**)&xH, g_xH);
    cudaGetSymbolAddress((void**)&fH, g_fH);
    cudaGetSymbolAddress((void**)&hH, g_hH);
    cudaGetSymbolAddress((void**)&wth, g_wth);
    cudaGetSymbolAddress((void**)&wtl, g_wtl);
    cudaGetSymbolAddress((void**)&el, g_el);
    cudaGetSymbolAddress((void**)&er, g_er);
    cudaGetSymbolAddress((void**)&deg, g_deg);
    cudaGetSymbolAddress((void**)&off, g_off);
    cudaGetSymbolAddress((void**)&esrc, g_esrc);
    cudaGetSymbolAddress((void**)&bsum, g_bsum);
    cudaGetSymbolAddress((void**)&boff, g_boff);

    const int SM128 = (128 + 2 * 128) * 136 * 2;   // 104448 B
    const int SM32  = (128 + 2 * 32)  * 136 * 2;   // 52224 B
    cudaFuncSetAttribute((const void*)gemm_mma_kernel<128>,
                         cudaFuncAttributeMaxDynamicSharedMemorySize, SM128);
    cudaFuncSetAttribute((const void*)gemm_mma_kernel<32>,
                         cudaFuncAttributeMaxDynamicSharedMemorySize, SM32);

    const int gemm_blocks = (N + 127) / 128;
    const int eblk = (E + 255) / 256;
    const int nb   = (N + 1023) / 1024;
    const int edge_blocks = (N * 32 + 255) / 256;

    // ---------------- prep: conversions + CSR build ----------------
    conv_x_kernel<<<(N * 32 + 255) / 256, 256>>>(x, xH, N * 32);
    conv_w_kernel<<<64, 256>>>(W1, wth, wtl, 128);
    conv_w_kernel<<<64, 256>>>(W2, wth + 16384, wtl + 16384, 128);
    conv_w_kernel<<<16, 256>>>(W3, wth + 32768, wtl + 32768, 32);

    cudaMemsetAsync(deg, 0, (size_t)N * sizeof(int));
    hist_kernel<<<eblk, 256>>>(dst, deg, E);
    bsum_kernel<<<nb, 256>>>(deg, bsum, N);
    bscan_kernel<<<1, 128>>>(bsum, boff, off, nb, N);
    scan_chunk_kernel<<<nb, 256>>>(deg, boff, off, N);
    cudaMemsetAsync(deg, 0, (size_t)N * sizeof(int));
    scatter_kernel<<<eblk, 256>>>(src, dst, off, deg, esrc, E);

    // ---------------- Layer 1 ----------------
    gemm_mma_kernel<128><<<gemm_blocks, 256, SM128>>>(
        xH, wth, wtl, al1, ar1, fH, el, er, N);
    edge_csr_kernel<4, true, true><<<edge_blocks, 256>>>(
        fH, el, er, off, esrc, b1, hH, N);

    // ---------------- Layer 2 ----------------
    gemm_mma_kernel<128><<<gemm_blocks, 256, SM128>>>(
        hH, wth + 16384, wtl + 16384, al2, ar2, fH, el, er, N);
    edge_csr_kernel<4, true, true><<<edge_blocks, 256>>>(
        fH, el, er, off, esrc, b2, hH, N);

    // ---------------- Layer 3 ----------------
    gemm_mma_kernel<32><<<gemm_blocks, 256, SM32>>>(
        hH, wth + 32768, wtl + 32768, al3, ar3, fH, el, er, N);
    edge_csr_kernel<1, false, false><<<edge_blocks, 256>>>(
        fH, el, er, off, esrc, b3, out, N);
}